// round 2
// baseline (speedup 1.0000x reference)
#include <cuda_runtime.h>
#include <cuda_bf16.h>

#define BB 2048
#define TT 128
#define DD 512

// Scratch: gi transposed as [(t*3+g)*B + b]  -> coalesced reads in the scan.
__device__ float g_giT[3 * TT * BB];

// ---------------------------------------------------------------------------
// Kernel A: gi[b,t,g] = sum_d x[b,t,d] * w_ih[g,d]
// One warp per (b,t) row; weights held in registers; grid-stride loop.
// ---------------------------------------------------------------------------
__global__ void __launch_bounds__(256) gi_kernel(const float* __restrict__ x,
                                                 const float* __restrict__ w_ih) {
    const int lane   = threadIdx.x & 31;
    const int warp   = (blockIdx.x * blockDim.x + threadIdx.x) >> 5;
    const int nwarps = (gridDim.x * blockDim.x) >> 5;

    // Lane handles float4 slots j = lane + 32*i, i in [0,4)  (covers D=512).
    float4 wr[4], wz[4], wn[4];
    const float4* w4 = (const float4*)w_ih;
#pragma unroll
    for (int i = 0; i < 4; i++) {
        int j = lane + 32 * i;
        wr[i] = w4[0 * (DD / 4) + j];
        wz[i] = w4[1 * (DD / 4) + j];
        wn[i] = w4[2 * (DD / 4) + j];
    }

    const int total = BB * TT;
    for (int row = warp; row < total; row += nwarps) {
        // row = t*B + b  -> consecutive warps write consecutive b (coalesced giT stores)
        const int t = row >> 11;          // row / 2048
        const int b = row & (BB - 1);     // row % 2048
        const float4* xr = (const float4*)(x + ((size_t)b * TT + t) * DD);

        float sr = 0.f, sz = 0.f, sn = 0.f;
#pragma unroll
        for (int i = 0; i < 4; i++) {
            float4 v = xr[lane + 32 * i];
            sr += v.x * wr[i].x + v.y * wr[i].y + v.z * wr[i].z + v.w * wr[i].w;
            sz += v.x * wz[i].x + v.y * wz[i].y + v.z * wz[i].z + v.w * wz[i].w;
            sn += v.x * wn[i].x + v.y * wn[i].y + v.z * wn[i].z + v.w * wn[i].w;
        }
#pragma unroll
        for (int off = 16; off; off >>= 1) {
            sr += __shfl_down_sync(0xffffffffu, sr, off);
            sz += __shfl_down_sync(0xffffffffu, sz, off);
            sn += __shfl_down_sync(0xffffffffu, sn, off);
        }
        if (lane == 0) {
            g_giT[(t * 3 + 0) * BB + b] = sr;
            g_giT[(t * 3 + 1) * BB + b] = sz;
            g_giT[(t * 3 + 2) * BB + b] = sn;
        }
    }
}

// ---------------------------------------------------------------------------
// Kernel B: sequential GRU scan (one thread per batch row) + mean over B.
// ---------------------------------------------------------------------------
__global__ void __launch_bounds__(256) scan_kernel(const float* __restrict__ h0,
                                                   const float* __restrict__ w_hh,
                                                   const float* __restrict__ b_ih,
                                                   const float* __restrict__ b_hh,
                                                   float* __restrict__ out) {
    const int b = blockIdx.x * blockDim.x + threadIdx.x;   // 0..2047

    const float whh0 = w_hh[0], whh1 = w_hh[1], whh2 = w_hh[2];
    const float c0 = b_ih[0] + b_hh[0];
    const float c1 = b_ih[1] + b_hh[1];
    const float ci2 = b_ih[2];
    const float ch2 = b_hh[2];

    float h = h0[b];                     // h0 is [1, B, 1]
    const float inv = 1.0f / (float)BB;

#pragma unroll 4
    for (int t = 0; t < TT; t++) {
        const float gr = g_giT[(t * 3 + 0) * BB + b];
        const float gz = g_giT[(t * 3 + 1) * BB + b];
        const float gn = g_giT[(t * 3 + 2) * BB + b];

        const float ar = gr + c0 + h * whh0;
        const float az = gz + c1 + h * whh1;
        const float r  = 1.0f / (1.0f + __expf(-ar));
        const float z  = 1.0f / (1.0f + __expf(-az));
        const float ghn = h * whh2 + ch2;
        const float n  = tanhf(gn + ci2 + r * ghn);
        h = n + z * (h - n);             // (1-z)*n + z*h

        // Mean over B: warp-reduce (off the h-dependency chain), one atomic per warp.
        float s = h;
#pragma unroll
        for (int off = 16; off; off >>= 1)
            s += __shfl_down_sync(0xffffffffu, s, off);
        if ((threadIdx.x & 31) == 0)
            atomicAdd(out + t, s * inv);
    }
}

// ---------------------------------------------------------------------------
// Launch: inputs per metadata order: x, h0, w_ih, w_hh, b_ih, b_hh
// ---------------------------------------------------------------------------
extern "C" void kernel_launch(void* const* d_in, const int* in_sizes, int n_in,
                              void* d_out, int out_size) {
    const float* x    = (const float*)d_in[0];
    const float* h0   = (const float*)d_in[1];
    const float* w_ih = (const float*)d_in[2];
    const float* w_hh = (const float*)d_in[3];
    const float* b_ih = (const float*)d_in[4];
    const float* b_hh = (const float*)d_in[5];
    float* out = (float*)d_out;

    // out is poisoned 0xAA; atomics accumulate into it -> zero first.
    cudaMemsetAsync(out, 0, (size_t)out_size * sizeof(float));

    // Kernel A: 4096 blocks x 256 threads = 32768 warps; 8 rows per warp.
    gi_kernel<<<4096, 256>>>(x, w_ih);

    // Kernel B: 2048 threads total.
    scan_kernel<<<BB / 256, 256>>>(h0, w_hh, b_ih, b_hh, out);
}

// round 3
// speedup vs baseline: 1.3253x; 1.3253x over previous
#include <cuda_runtime.h>
#include <cuda_bf16.h>

#define BB 2048
#define TT 128
#define DD 512

// Scratch: gi transposed as [(t*3+g)*B + b]  -> coalesced reads in the scan.
__device__ float g_giT[3 * TT * BB];

__device__ __forceinline__ float tanh_fast(float x) {
    float y;
    asm("tanh.approx.f32 %0, %1;" : "=f"(y) : "f"(x));
    return y;
}

// ---------------------------------------------------------------------------
// Kernel A: gi[b,t,g] = sum_d x[b,t,d] * w_ih[g,d]
// One warp per (b,t) row; weights held in registers; grid-stride loop.
// HBM-bound: 512 MB of x read once, ~5.9 TB/s achieved.
// ---------------------------------------------------------------------------
__global__ void __launch_bounds__(256) gi_kernel(const float* __restrict__ x,
                                                 const float* __restrict__ w_ih) {
    const int lane   = threadIdx.x & 31;
    const int warp   = (blockIdx.x * blockDim.x + threadIdx.x) >> 5;
    const int nwarps = (gridDim.x * blockDim.x) >> 5;

    // Lane handles float4 slots j = lane + 32*i, i in [0,4)  (covers D=512).
    float4 wr[4], wz[4], wn[4];
    const float4* w4 = (const float4*)w_ih;
#pragma unroll
    for (int i = 0; i < 4; i++) {
        int j = lane + 32 * i;
        wr[i] = w4[0 * (DD / 4) + j];
        wz[i] = w4[1 * (DD / 4) + j];
        wn[i] = w4[2 * (DD / 4) + j];
    }

    const int total = BB * TT;
    for (int row = warp; row < total; row += nwarps) {
        // row = t*B + b  -> consecutive warps write consecutive b (coalesced giT stores)
        const int t = row >> 11;          // row / 2048
        const int b = row & (BB - 1);     // row % 2048
        const float4* xr = (const float4*)(x + ((size_t)b * TT + t) * DD);

        float sr = 0.f, sz = 0.f, sn = 0.f;
#pragma unroll
        for (int i = 0; i < 4; i++) {
            float4 v = xr[lane + 32 * i];
            sr += v.x * wr[i].x + v.y * wr[i].y + v.z * wr[i].z + v.w * wr[i].w;
            sz += v.x * wz[i].x + v.y * wz[i].y + v.z * wz[i].z + v.w * wz[i].w;
            sn += v.x * wn[i].x + v.y * wn[i].y + v.z * wn[i].z + v.w * wn[i].w;
        }
#pragma unroll
        for (int off = 16; off; off >>= 1) {
            sr += __shfl_down_sync(0xffffffffu, sr, off);
            sz += __shfl_down_sync(0xffffffffu, sz, off);
            sn += __shfl_down_sync(0xffffffffu, sn, off);
        }
        if (lane == 0) {
            g_giT[(t * 3 + 0) * BB + b] = sr;
            g_giT[(t * 3 + 1) * BB + b] = sz;
            g_giT[(t * 3 + 2) * BB + b] = sn;
        }
    }
}

// ---------------------------------------------------------------------------
// Kernel B: sequential GRU scan (one thread per batch row) + mean over B.
// All transcendentals via MUFU.TANH; gi loads prefetched one step ahead.
// sigmoid(x) = 0.5*tanh(0.5x) + 0.5 ; half-scalings folded into constants.
// ---------------------------------------------------------------------------
__global__ void __launch_bounds__(32) scan_kernel(const float* __restrict__ h0,
                                                  const float* __restrict__ w_hh,
                                                  const float* __restrict__ b_ih,
                                                  const float* __restrict__ b_hh,
                                                  float* __restrict__ out) {
    const int b = blockIdx.x * blockDim.x + threadIdx.x;   // 0..2047

    // Half-scaled recurrent weights/biases for the sigmoid-as-tanh trick.
    const float whh0h = 0.5f * w_hh[0];
    const float whh1h = 0.5f * w_hh[1];
    const float whh2  = w_hh[2];
    const float c0h   = 0.5f * (b_ih[0] + b_hh[0]);
    const float c1h   = 0.5f * (b_ih[1] + b_hh[1]);
    const float ci2   = b_ih[2];
    const float ch2   = b_hh[2];

    float h = h0[b];
    const float inv = 1.0f / (float)BB;

    // Prefetch t=0 (half-scaled r/z inputs computed off-chain).
    float gr = g_giT[0 * BB + b];
    float gz = g_giT[1 * BB + b];
    float gn = g_giT[2 * BB + b];

#pragma unroll 8
    for (int t = 0; t < TT; t++) {
        // Prefetch next step's gi (independent of h -> overlaps the chain).
        float ngr = 0.f, ngz = 0.f, ngn = 0.f;
        if (t + 1 < TT) {
            ngr = g_giT[((t + 1) * 3 + 0) * BB + b];
            ngz = g_giT[((t + 1) * 3 + 1) * BB + b];
            ngn = g_giT[((t + 1) * 3 + 2) * BB + b];
        }

        // Off-chain: fold 0.5 into the gate pre-activations.
        const float grh = fmaf(gr, 0.5f, c0h);
        const float gzh = fmaf(gz, 0.5f, c1h);
        const float gnc = gn + ci2;

        // r = sigmoid(gr + c0 + h*whh0) = 0.5*tanh(grh + h*whh0h) + 0.5
        const float r = fmaf(tanh_fast(fmaf(h, whh0h, grh)), 0.5f, 0.5f);
        const float z = fmaf(tanh_fast(fmaf(h, whh1h, gzh)), 0.5f, 0.5f);
        const float ghn = fmaf(h, whh2, ch2);            // off r/z chain
        const float n = tanh_fast(fmaf(r, ghn, gnc));
        h = fmaf(z, h - n, n);                           // (1-z)*n + z*h

        // Mean over B: shuffles don't feed the h chain.
        float s = h;
#pragma unroll
        for (int off = 16; off; off >>= 1)
            s += __shfl_down_sync(0xffffffffu, s, off);
        if ((threadIdx.x & 31) == 0)
            atomicAdd(out + t, s * inv);

        gr = ngr; gz = ngz; gn = ngn;
    }
}

// ---------------------------------------------------------------------------
// Launch: inputs per metadata order: x, h0, w_ih, w_hh, b_ih, b_hh
// ---------------------------------------------------------------------------
extern "C" void kernel_launch(void* const* d_in, const int* in_sizes, int n_in,
                              void* d_out, int out_size) {
    const float* x    = (const float*)d_in[0];
    const float* h0   = (const float*)d_in[1];
    const float* w_ih = (const float*)d_in[2];
    const float* w_hh = (const float*)d_in[3];
    const float* b_ih = (const float*)d_in[4];
    const float* b_hh = (const float*)d_in[5];
    float* out = (float*)d_out;

    // out is poisoned 0xAA; atomics accumulate into it -> zero first.
    cudaMemsetAsync(out, 0, (size_t)out_size * sizeof(float));

    // Kernel A: 4096 blocks x 256 threads = 32768 warps; 8 rows per warp.
    gi_kernel<<<4096, 256>>>(x, w_ih);

    // Kernel B: 2048 threads spread over 64 SMs (1 warp per block).
    scan_kernel<<<64, 32>>>(h0, w_hh, b_ih, b_hh, out);
}

// round 5
// speedup vs baseline: 1.5035x; 1.1345x over previous
#include <cuda_runtime.h>
#include <cuda_bf16.h>

#define BB 2048
#define TT 128
#define DD 512
#define GRP 8                     // software-pipeline group size (steps)
#define NGRP (TT / GRP)           // 16 groups

// Scratch: gi transposed as [(t*3+g)*B + b]  -> coalesced reads in the scan.
__device__ float g_giT[3 * TT * BB];

__device__ __forceinline__ float tanh_fast(float x) {
    float y;
    asm("tanh.approx.f32 %0, %1;" : "=f"(y) : "f"(x));
    return y;
}

// ---------------------------------------------------------------------------
// Kernel A: gi[b,t,g] = sum_d x[b,t,d] * w_ih[g,d]
// One warp per (b,t) row; weights held in registers; grid-stride loop.
// HBM-bound: 512 MB of x read once, ~5.9 TB/s achieved (near LTS cap).
// ---------------------------------------------------------------------------
__global__ void __launch_bounds__(256) gi_kernel(const float* __restrict__ x,
                                                 const float* __restrict__ w_ih) {
    const int lane   = threadIdx.x & 31;
    const int warp   = (blockIdx.x * blockDim.x + threadIdx.x) >> 5;
    const int nwarps = (gridDim.x * blockDim.x) >> 5;

    float4 wr[4], wz[4], wn[4];
    const float4* w4 = (const float4*)w_ih;
#pragma unroll
    for (int i = 0; i < 4; i++) {
        int j = lane + 32 * i;
        wr[i] = w4[0 * (DD / 4) + j];
        wz[i] = w4[1 * (DD / 4) + j];
        wn[i] = w4[2 * (DD / 4) + j];
    }

    const int total = BB * TT;
    for (int row = warp; row < total; row += nwarps) {
        const int t = row >> 11;          // row / 2048
        const int b = row & (BB - 1);     // row % 2048
        const float4* xr = (const float4*)(x + ((size_t)b * TT + t) * DD);

        float sr = 0.f, sz = 0.f, sn = 0.f;
#pragma unroll
        for (int i = 0; i < 4; i++) {
            float4 v = xr[lane + 32 * i];
            sr += v.x * wr[i].x + v.y * wr[i].y + v.z * wr[i].z + v.w * wr[i].w;
            sz += v.x * wz[i].x + v.y * wz[i].y + v.z * wz[i].z + v.w * wz[i].w;
            sn += v.x * wn[i].x + v.y * wn[i].y + v.z * wn[i].z + v.w * wn[i].w;
        }
#pragma unroll
        for (int off = 16; off; off >>= 1) {
            sr += __shfl_down_sync(0xffffffffu, sr, off);
            sz += __shfl_down_sync(0xffffffffu, sz, off);
            sn += __shfl_down_sync(0xffffffffu, sn, off);
        }
        if (lane == 0) {
            g_giT[(t * 3 + 0) * BB + b] = sr;
            g_giT[(t * 3 + 1) * BB + b] = sz;
            g_giT[(t * 3 + 2) * BB + b] = sn;
        }
    }
}

// ---------------------------------------------------------------------------
// Kernel B: sequential GRU scan, one thread per batch row.
// - Double-buffered register groups of 8 steps: all 24 gi loads for group g+1
//   issue before group g's chain -> L2 latency fully hidden.
// - Per-step: off-chain STS of h into smem; reduction done AFTER the loop
//   (pipelined over the 128 independent t's).
// - sigmoid(x) = 0.5*tanh(0.5x)+0.5, all transcendentals via MUFU.TANH.
// ---------------------------------------------------------------------------
__global__ void __launch_bounds__(32) scan_kernel(const float* __restrict__ h0,
                                                  const float* __restrict__ w_hh,
                                                  const float* __restrict__ b_ih,
                                                  const float* __restrict__ b_hh,
                                                  float* __restrict__ out) {
    __shared__ float h_hist[TT * 32];               // 16 KB: [t][lane]
    const int lane = threadIdx.x;                   // 0..31
    const int b = blockIdx.x * 32 + lane;           // 0..2047

    const float whh0h = 0.5f * w_hh[0];
    const float whh1h = 0.5f * w_hh[1];
    const float whh2  = w_hh[2];
    const float c0h   = 0.5f * (b_ih[0] + b_hh[0]);
    const float c1h   = 0.5f * (b_ih[1] + b_hh[1]);
    const float cn    = b_ih[2] + 0.0f;             // n-gate input bias
    const float ch2   = b_hh[2];

    float h = h0[b];

    float gr[2][GRP], gz[2][GRP], gn[2][GRP];

    // Prologue: load group 0 into buffer 0.
#pragma unroll
    for (int k = 0; k < GRP; k++) {
        gr[0][k] = g_giT[(k * 3 + 0) * BB + b];
        gz[0][k] = g_giT[(k * 3 + 1) * BB + b];
        gn[0][k] = g_giT[(k * 3 + 2) * BB + b];
    }

#pragma unroll
    for (int g = 0; g < NGRP; g++) {
        const int cb = g & 1, nb = cb ^ 1;

        // Issue next group's loads first (in-order issue -> latency hidden
        // behind this group's ~420-cycle dependency chain).
        if (g + 1 < NGRP) {
#pragma unroll
            for (int k = 0; k < GRP; k++) {
                const int t = (g + 1) * GRP + k;
                gr[nb][k] = g_giT[(t * 3 + 0) * BB + b];
                gz[nb][k] = g_giT[(t * 3 + 1) * BB + b];
                gn[nb][k] = g_giT[(t * 3 + 2) * BB + b];
            }
        }

#pragma unroll
        for (int k = 0; k < GRP; k++) {
            const int t = g * GRP + k;
            // Off-chain pre-activation folds.
            const float grh = fmaf(gr[cb][k], 0.5f, c0h);
            const float gzh = fmaf(gz[cb][k], 0.5f, c1h);
            const float gnc = gn[cb][k] + cn;

            const float r = fmaf(tanh_fast(fmaf(h, whh0h, grh)), 0.5f, 0.5f);
            const float z = fmaf(tanh_fast(fmaf(h, whh1h, gzh)), 0.5f, 0.5f);
            const float ghn = fmaf(h, whh2, ch2);
            const float n = tanh_fast(fmaf(r, ghn, gnc));
            h = fmaf(z, h - n, n);                  // (1-z)*n + z*h

            h_hist[t * 32 + lane] = h;              // off-chain STS
        }
    }

    // Post-loop reduction: 128 independent t's, pipelined.
    const float inv = 1.0f / (float)BB;
#pragma unroll 4
    for (int t = 0; t < TT; t++) {
        float s = h_hist[t * 32 + lane];            // each lane reads its own write
#pragma unroll
        for (int off = 16; off; off >>= 1)
            s += __shfl_down_sync(0xffffffffu, s, off);
        if (lane == 0)
            atomicAdd(out + t, s * inv);
    }
}

// ---------------------------------------------------------------------------
// Launch: inputs per metadata order: x, h0, w_ih, w_hh, b_ih, b_hh
// ---------------------------------------------------------------------------
extern "C" void kernel_launch(void* const* d_in, const int* in_sizes, int n_in,
                              void* d_out, int out_size) {
    const float* x    = (const float*)d_in[0];
    const float* h0   = (const float*)d_in[1];
    const float* w_ih = (const float*)d_in[2];
    const float* w_hh = (const float*)d_in[3];
    const float* b_ih = (const float*)d_in[4];
    const float* b_hh = (const float*)d_in[5];
    float* out = (float*)d_out;

    cudaMemsetAsync(out, 0, (size_t)out_size * sizeof(float));

    gi_kernel<<<4096, 256>>>(x, w_ih);
    scan_kernel<<<BB / 32, 32>>>(h0, w_hh, b_ih, b_hh, out);
}

// round 7
// speedup vs baseline: 1.8420x; 1.2252x over previous
#include <cuda_runtime.h>
#include <cuda_bf16.h>

#define BB 2048
#define TT 128
#define DD 512

// Scratch: gi transposed as [(t*3+g)*B + b]  -> coalesced reads in the scan.
__device__ float g_giT[3 * TT * BB];

__device__ __forceinline__ float tanh_fast(float x) {
    float y;
    asm("tanh.approx.f32 %0, %1;" : "=f"(y) : "f"(x));
    return y;
}

// ---------------------------------------------------------------------------
// Kernel A: gi[b,t,g] = sum_d x[b,t,d] * w_ih[g,d]
// One warp per 2 rows (interleaved -> 8 outstanding LDG.128), weights in regs.
// HBM-bound: 512 MB of x read once.
// ---------------------------------------------------------------------------
__global__ void __launch_bounds__(256) gi_kernel(const float* __restrict__ x,
                                                 const float* __restrict__ w_ih) {
    const int lane   = threadIdx.x & 31;
    const int warp   = (blockIdx.x * blockDim.x + threadIdx.x) >> 5;
    const int nwarps = (gridDim.x * blockDim.x) >> 5;

    float4 wr[4], wz[4], wn[4];
    const float4* w4 = (const float4*)w_ih;
#pragma unroll
    for (int i = 0; i < 4; i++) {
        int j = lane + 32 * i;
        wr[i] = w4[0 * (DD / 4) + j];
        wz[i] = w4[1 * (DD / 4) + j];
        wn[i] = w4[2 * (DD / 4) + j];
    }

    const int total = BB * TT;
    for (int row = warp * 2; row < total; row += nwarps * 2) {
        const int r0 = row, r1 = row + 1;
        const int t0 = r0 >> 11, b0 = r0 & (BB - 1);
        const int t1 = r1 >> 11, b1 = r1 & (BB - 1);
        const float4* xr0 = (const float4*)(x + ((size_t)b0 * TT + t0) * DD);
        const float4* xr1 = (const float4*)(x + ((size_t)b1 * TT + t1) * DD);

        // Front-batch all 8 loads (MLP=8 per lane).
        float4 v0[4], v1[4];
#pragma unroll
        for (int i = 0; i < 4; i++) v0[i] = xr0[lane + 32 * i];
#pragma unroll
        for (int i = 0; i < 4; i++) v1[i] = xr1[lane + 32 * i];

        float sr0 = 0.f, sz0 = 0.f, sn0 = 0.f;
        float sr1 = 0.f, sz1 = 0.f, sn1 = 0.f;
#pragma unroll
        for (int i = 0; i < 4; i++) {
            sr0 += v0[i].x * wr[i].x + v0[i].y * wr[i].y + v0[i].z * wr[i].z + v0[i].w * wr[i].w;
            sz0 += v0[i].x * wz[i].x + v0[i].y * wz[i].y + v0[i].z * wz[i].z + v0[i].w * wz[i].w;
            sn0 += v0[i].x * wn[i].x + v0[i].y * wn[i].y + v0[i].z * wn[i].z + v0[i].w * wn[i].w;
            sr1 += v1[i].x * wr[i].x + v1[i].y * wr[i].y + v1[i].z * wr[i].z + v1[i].w * wr[i].w;
            sz1 += v1[i].x * wz[i].x + v1[i].y * wz[i].y + v1[i].z * wz[i].z + v1[i].w * wz[i].w;
            sn1 += v1[i].x * wn[i].x + v1[i].y * wn[i].y + v1[i].z * wn[i].z + v1[i].w * wn[i].w;
        }
#pragma unroll
        for (int off = 16; off; off >>= 1) {
            sr0 += __shfl_down_sync(0xffffffffu, sr0, off);
            sz0 += __shfl_down_sync(0xffffffffu, sz0, off);
            sn0 += __shfl_down_sync(0xffffffffu, sn0, off);
            sr1 += __shfl_down_sync(0xffffffffu, sr1, off);
            sz1 += __shfl_down_sync(0xffffffffu, sz1, off);
            sn1 += __shfl_down_sync(0xffffffffu, sn1, off);
        }
        if (lane == 0) {
            g_giT[(t0 * 3 + 0) * BB + b0] = sr0;
            g_giT[(t0 * 3 + 1) * BB + b0] = sz0;
            g_giT[(t0 * 3 + 2) * BB + b0] = sn0;
            g_giT[(t1 * 3 + 0) * BB + b1] = sr1;
            g_giT[(t1 * 3 + 1) * BB + b1] = sz1;
            g_giT[(t1 * 3 + 2) * BB + b1] = sn1;
        }
    }
}

// ---------------------------------------------------------------------------
// Kernel B: GRU scan. Block = 256 threads, handles 32 batch rows.
// Phase 1: all 8 warps stage the block's 48 KB gi tile into smem (huge MLP).
// Phase 2: warp 0 runs the serial scan from smem (LDS hidden by 1-step
//          register prefetch under the ~48-cycle tanh chain). h written into
//          the consumed gi slot.
// Phase 3: all 8 warps reduce over b (16 t's per warp) -> atomicAdd.
// ---------------------------------------------------------------------------
__global__ void __launch_bounds__(256) scan_kernel(const float* __restrict__ h0,
                                                   const float* __restrict__ w_hh,
                                                   const float* __restrict__ b_ih,
                                                   const float* __restrict__ b_hh,
                                                   float* __restrict__ out) {
    __shared__ float sg[TT * 3 * 32];               // 48 KB: [(t*3+g)*32 + lane]
    const int tid  = threadIdx.x;
    const int lane = tid & 31;
    const int wid  = tid >> 5;
    const int b0   = blockIdx.x * 32;

    // Phase 1: cooperative tile load. 384 rows of 32 floats; warp w takes
    // rows w, w+8, ... (48 independent 128B loads per warp).
#pragma unroll 8
    for (int r = wid; r < TT * 3; r += 8)
        sg[r * 32 + lane] = g_giT[(size_t)r * BB + b0 + lane];
    __syncthreads();

    // Phase 2: serial scan by warp 0.
    if (wid == 0) {
        const float whh0h = 0.5f * w_hh[0];
        const float whh1h = 0.5f * w_hh[1];
        const float whh2  = w_hh[2];
        const float c0h   = 0.5f * (b_ih[0] + b_hh[0]);
        const float c1h   = 0.5f * (b_ih[1] + b_hh[1]);
        const float cn    = b_ih[2];
        const float ch2   = b_hh[2];

        float h = h0[b0 + lane];

        float gr = sg[0 * 32 + lane];
        float gz = sg[1 * 32 + lane];
        float gn = sg[2 * 32 + lane];

#pragma unroll
        for (int t = 0; t < TT; t++) {
            // Prefetch next step (off-chain LDS, hidden under the chain).
            float ngr = 0.f, ngz = 0.f, ngn = 0.f;
            if (t + 1 < TT) {
                ngr = sg[((t + 1) * 3 + 0) * 32 + lane];
                ngz = sg[((t + 1) * 3 + 1) * 32 + lane];
                ngn = sg[((t + 1) * 3 + 2) * 32 + lane];
            }

            // Off-chain folds.
            const float grh = fmaf(gr, 0.5f, c0h);
            const float gzh = fmaf(gz, 0.5f, c1h);
            const float gnc = gn + cn;

            // Chain: FFMA -> MUFU -> FFMA -> MUFU -> FSUB -> FFMA (~48 cy).
            const float th_r = tanh_fast(fmaf(h, whh0h, grh));
            const float ghn  = fmaf(h, whh2, ch2);          // parallel to th_r
            const float ghnh = 0.5f * ghn;
            // r*ghn = (0.5*th_r + 0.5)*ghn = th_r*ghnh + ghnh
            const float n = tanh_fast(fmaf(th_r, ghnh, gnc + ghnh));
            const float z = fmaf(tanh_fast(fmaf(h, whh1h, gzh)), 0.5f, 0.5f);
            h = fmaf(z, h - n, n);                          // (1-z)*n + z*h

            sg[(t * 3 + 2) * 32 + lane] = h;                // reuse consumed slot
            gr = ngr; gz = ngz; gn = ngn;
        }
    }
    __syncthreads();

    // Phase 3: reduction over lanes, 16 t's per warp, all warps.
    const float inv = 1.0f / (float)BB;
#pragma unroll
    for (int j = 0; j < 16; j++) {
        const int t = wid * 16 + j;
        float s = sg[(t * 3 + 2) * 32 + lane];
#pragma unroll
        for (int off = 16; off; off >>= 1)
            s += __shfl_down_sync(0xffffffffu, s, off);
        if (lane == 0)
            atomicAdd(out + t, s * inv);
    }
}

// ---------------------------------------------------------------------------
// Launch: inputs per metadata order: x, h0, w_ih, w_hh, b_ih, b_hh
// ---------------------------------------------------------------------------
extern "C" void kernel_launch(void* const* d_in, const int* in_sizes, int n_in,
                              void* d_out, int out_size) {
    const float* x    = (const float*)d_in[0];
    const float* h0   = (const float*)d_in[1];
    const float* w_ih = (const float*)d_in[2];
    const float* w_hh = (const float*)d_in[3];
    const float* b_ih = (const float*)d_in[4];
    const float* b_hh = (const float*)d_in[5];
    float* out = (float*)d_out;

    cudaMemsetAsync(out, 0, (size_t)out_size * sizeof(float));

    gi_kernel<<<4096, 256>>>(x, w_ih);
    scan_kernel<<<BB / 32, 256>>>(h0, w_hh, b_ih, b_hh, out);
}